// round 1
// baseline (speedup 1.0000x reference)
#include <cuda_runtime.h>
#include <math.h>

#define BB 2
#define QQ 75
#define NN 5
#define KK 1
#define TT 196
#define CC 384
#define HH 1536
#define KT (KK*TT)
#define BQ (BB*QQ)
#define TEMPF 10.0f

// ---------------- scratch (no allocation allowed) ----------------
__device__ float g_cls_mean[BB*NN*CC];
__device__ float g_task_mean[BB*CC];
__device__ float g_wt[BB*CC];
__device__ float g_wc[BB*NN*CC];
__device__ float g_ns[BB*NN*KT];
__device__ float g_xs_hat[BB*NN*CC];   // normalized reweighted shot prototype
__device__ float g_xs2_hat[BB*NN*CC];  // normalized plain shot prototype

template<int NV>
__device__ __forceinline__ void warpRed(float* v) {
#pragma unroll
    for (int off = 16; off; off >>= 1) {
#pragma unroll
        for (int k = 0; k < NV; k++)
            v[k] += __shfl_xor_sync(0xffffffffu, v[k], off);
    }
}

__device__ __forceinline__ float sigm(float x) {
    return 1.0f / (1.0f + __expf(-x));
}

// ---------------- Kernel A: cls_mean[b,n,c] = mean_{k,t} feat_shot ----------------
__global__ void kMeanShot(const float* __restrict__ fshot) {
    int bn = blockIdx.x, c = threadIdx.x;
    const float* p = fshot + (size_t)bn * KT * CC + c;
    float s = 0.0f;
    for (int t = 0; t < KT; t++) s += p[(size_t)t * CC];
    g_cls_mean[bn * CC + c] = s * (1.0f / KT);
}

// ---------------- Kernel A2: task_mean[b,c] = mean_n cls_mean ----------------
__global__ void kTaskMean() {
    int b = blockIdx.x, c = threadIdx.x;
    float s = 0.0f;
#pragma unroll
    for (int n = 0; n < NN; n++) s += g_cls_mean[(b * NN + n) * CC + c];
    g_task_mean[b * CC + c] = s * (1.0f / NN);
}

// ---------------- Kernel B: both MLPs. blocks 0..B-1 = task rows, B..B+B*N-1 = cls rows ----------------
__global__ __launch_bounds__(CC, 1) void kMLP(
    const float* __restrict__ w1t, const float* __restrict__ b1t,
    const float* __restrict__ w2t, const float* __restrict__ b2t,
    const float* __restrict__ w1c, const float* __restrict__ b1c,
    const float* __restrict__ w2c, const float* __restrict__ b2c) {
    __shared__ float sx[CC];
    __shared__ float hid[HH];
    int row = blockIdx.x, tid = threadIdx.x;
    const float *in, *w1, *b1, *w2, *b2;
    float* outp;
    bool sig;
    if (row < BB) {
        in = g_task_mean + row * CC;
        w1 = w1t; b1 = b1t; w2 = w2t; b2 = b2t;
        outp = g_wt + row * CC; sig = false;
    } else {
        int r = row - BB;
        in = g_cls_mean + r * CC;
        w1 = w1c; b1 = b1c; w2 = w2c; b2 = b2c;
        outp = g_wc + r * CC; sig = true;
    }
    sx[tid] = in[tid];
    __syncthreads();

    float h0 = b1[tid], h1 = b1[tid + CC], h2 = b1[tid + 2 * CC], h3 = b1[tid + 3 * CC];
    for (int c = 0; c < CC; c++) {
        float xv = sx[c];
        const float* wr = w1 + (size_t)c * HH;
        h0 += xv * wr[tid];
        h1 += xv * wr[tid + CC];
        h2 += xv * wr[tid + 2 * CC];
        h3 += xv * wr[tid + 3 * CC];
    }
    hid[tid]          = fmaxf(h0, 0.0f);
    hid[tid + CC]     = fmaxf(h1, 0.0f);
    hid[tid + 2 * CC] = fmaxf(h2, 0.0f);
    hid[tid + 3 * CC] = fmaxf(h3, 0.0f);
    __syncthreads();

    float o = b2[tid];
    for (int j = 0; j < HH; j++) o += hid[j] * w2[(size_t)j * CC + tid];
    if (sig) o = sigm(o);
    outp[tid] = o;
}

// ---------------- Kernel C: per (b,n) shot-side pass ----------------
// ns[b,n,t]; map_s; xs_rw -> normalized g_xs_hat; x_shot -> normalized g_xs2_hat
__global__ __launch_bounds__(CC, 1) void kShot(
    const float* __restrict__ fshot, const float* __restrict__ x_shot) {
    __shared__ __align__(16) float vv[CC];
    __shared__ float accs[CC];
    __shared__ float cw[12][2];
    __shared__ float tot[2];
    int bn = blockIdx.x, b = bn / NN, tid = threadIdx.x;
    int w = tid >> 5, lane = tid & 31;

    vv[tid]   = g_wc[bn * CC + tid] * g_wt[b * CC + tid];
    accs[tid] = 0.0f;
    __syncthreads();

    float acc[12];
#pragma unroll
    for (int e = 0; e < 12; e++) acc[e] = 0.0f;

    for (int t = w; t < KT; t += 12) {
        const float* fp = fshot + ((size_t)bn * KT + t) * CC + 4 * lane;
        float fv[12];
#pragma unroll
        for (int j = 0; j < 3; j++) {
            float4 u = *(const float4*)(fp + 128 * j);
            fv[4 * j] = u.x; fv[4 * j + 1] = u.y; fv[4 * j + 2] = u.z; fv[4 * j + 3] = u.w;
        }
        float r[2] = {0.0f, 0.0f};
#pragma unroll
        for (int j = 0; j < 3; j++) {
            float4 u = *(const float4*)(&vv[128 * j + 4 * lane]);
            r[0] += fv[4*j]*fv[4*j] + fv[4*j+1]*fv[4*j+1] + fv[4*j+2]*fv[4*j+2] + fv[4*j+3]*fv[4*j+3];
            r[1] += fv[4*j]*u.x + fv[4*j+1]*u.y + fv[4*j+2]*u.z + fv[4*j+3]*u.w;
        }
        warpRed<2>(r);
        if (lane == 0) g_ns[bn * KT + t] = sqrtf(r[0]);
        float ms = sigm(r[1]);
#pragma unroll
        for (int e = 0; e < 12; e++) acc[e] += fv[e] * ms;
    }
#pragma unroll
    for (int e = 0; e < 12; e++) {
        int c = 128 * (e >> 2) + (lane << 2) + (e & 3);
        atomicAdd(&accs[c], acc[e]);
    }
    __syncthreads();

    float xsr = g_wc[bn * CC + tid] * accs[tid] * (1.0f / KT);
    float xm = 0.0f;
#pragma unroll
    for (int k = 0; k < KK; k++) xm += x_shot[((size_t)bn * KK + k) * CC + tid];
    xm *= (1.0f / KK);

    float r2[2] = {xsr * xsr, xm * xm};
    warpRed<2>(r2);
    if (lane == 0) { cw[w][0] = r2[0]; cw[w][1] = r2[1]; }
    __syncthreads();
    if (tid < 2) {
        float s = 0.0f;
        for (int ww = 0; ww < 12; ww++) s += cw[ww][tid];
        tot[tid] = s;
    }
    __syncthreads();
    g_xs_hat[bn * CC + tid]  = xsr / (1e-16f + sqrtf(tot[0]));
    g_xs2_hat[bn * CC + tid] = xm / fmaxf(sqrtf(tot[1]), 1e-12f);
}

// ---------------- Kernel D: per (b,q) main fused pass ----------------
__global__ __launch_bounds__(CC, 1) void kMain(
    const float* __restrict__ fshot, const float* __restrict__ fq,
    const float* __restrict__ xq_in, float* __restrict__ out) {
    __shared__ __align__(16) float vv[NN * CC];
    __shared__ __align__(16) float wcs[NN * CC];
    __shared__ __align__(16) float xsh[NN * CC];
    __shared__ __align__(16) float xs2[NN * CC];
    __shared__ float accq[NN * CC];
    __shared__ float nss[NN * KT];
    __shared__ float cw[12][16];
    __shared__ float wmax[12 * NN];
    __shared__ float simtop[NN];
    __shared__ float tot[16];

    int bq = blockIdx.x, b = bq / QQ, q = bq % QQ, tid = threadIdx.x;
    int w = tid >> 5, lane = tid & 31;

    // preamble: load per-batch small tensors to smem
    {
        float wtb = g_wt[b * CC + tid];
#pragma unroll
        for (int n = 0; n < NN; n++) {
            float wcv = g_wc[(b * NN + n) * CC + tid];
            wcs[n * CC + tid] = wcv;
            vv[n * CC + tid]  = wcv * wtb;
            xsh[n * CC + tid] = g_xs_hat[(b * NN + n) * CC + tid];
            xs2[n * CC + tid] = g_xs2_hat[(b * NN + n) * CC + tid];
            accq[n * CC + tid] = 0.0f;
        }
        for (int i = tid; i < NN * KT; i += CC) nss[i] = g_ns[b * NN * KT + i];
    }
    __syncthreads();

    float acc[NN * 12];
#pragma unroll
    for (int e = 0; e < NN * 12; e++) acc[e] = 0.0f;
    float mx[NN];
#pragma unroll
    for (int n = 0; n < NN; n++) mx[n] = -3.4e38f;

    // warp-per-t streaming pass over feat_query row block (T x C)
    for (int t = w; t < TT; t += 12) {
        const float* fp = fq + (((size_t)(b * QQ + q)) * TT + t) * CC + 4 * lane;
        float fv[12];
#pragma unroll
        for (int j = 0; j < 3; j++) {
            float4 u = *(const float4*)(fp + 128 * j);
            fv[4 * j] = u.x; fv[4 * j + 1] = u.y; fv[4 * j + 2] = u.z; fv[4 * j + 3] = u.w;
        }
        float r[11];
#pragma unroll
        for (int k = 0; k < 11; k++) r[k] = 0.0f;
#pragma unroll
        for (int e = 0; e < 12; e++) r[0] += fv[e] * fv[e];
#pragma unroll
        for (int n = 0; n < NN; n++) {
            const float* fsp = fshot + (((size_t)(b * NN + n)) * KT + t) * CC + 4 * lane;
#pragma unroll
            for (int j = 0; j < 3; j++) {
                float4 u = *(const float4*)(fsp + 128 * j);
                r[1 + n] += fv[4*j]*u.x + fv[4*j+1]*u.y + fv[4*j+2]*u.z + fv[4*j+3]*u.w;
            }
        }
#pragma unroll
        for (int n = 0; n < NN; n++) {
#pragma unroll
            for (int j = 0; j < 3; j++) {
                float4 u = *(const float4*)(&vv[n * CC + 128 * j + 4 * lane]);
                r[6 + n] += fv[4*j]*u.x + fv[4*j+1]*u.y + fv[4*j+2]*u.z + fv[4*j+3]*u.w;
            }
        }
        warpRed<11>(r);
        float nq = sqrtf(r[0]);
#pragma unroll
        for (int n = 0; n < NN; n++) {
            float den = fmaxf(nq * nss[n * KT + t], 1e-8f);
            mx[n] = fmaxf(mx[n], r[1 + n] / den);
            float mq = sigm(r[6 + n]);
#pragma unroll
            for (int e = 0; e < 12; e++) acc[n * 12 + e] += fv[e] * mq;
        }
    }

    // combine per-warp accumulators
#pragma unroll
    for (int n = 0; n < NN; n++) {
#pragma unroll
        for (int e = 0; e < 12; e++) {
            int c = 128 * (e >> 2) + (lane << 2) + (e & 3);
            atomicAdd(&accq[n * CC + c], acc[n * 12 + e]);
        }
    }
    if (lane == 0) {
#pragma unroll
        for (int n = 0; n < NN; n++) wmax[w * NN + n] = mx[n];
    }
    __syncthreads();

    if (tid < NN) {
        float m = -3.4e38f;
        for (int ww = 0; ww < 12; ww++) m = fmaxf(m, wmax[ww * NN + tid]);
        simtop[tid] = m;
    }
    __syncthreads();
    if (tid == 0) {
        float s = 0.0f;
#pragma unroll
        for (int n = 0; n < NN; n++) s += simtop[n];
        s *= (1.0f / NN);
        out[bq] = s;            // logits
        out[BQ + bq] = s;       // logits_reweight (identical expression)
    }

    // final 16-value block reduce: |xq|^2, 5x dot(xq, xs2_hat), 5x |xq_rw|^2, 5x dot(xq_rw, xs_hat)
    float xqv = xq_in[(size_t)bq * CC + tid];
    float pv[16];
    pv[0] = xqv * xqv;
#pragma unroll
    for (int n = 0; n < NN; n++) {
        float xqr = wcs[n * CC + tid] * accq[n * CC + tid] * (1.0f / TT);
        pv[1 + n]  = xqv * xs2[n * CC + tid];
        pv[6 + n]  = xqr * xqr;
        pv[11 + n] = xqr * xsh[n * CC + tid];
    }
    warpRed<16>(pv);
    if (lane == 0) {
#pragma unroll
        for (int k = 0; k < 16; k++) cw[w][k] = pv[k];
    }
    __syncthreads();
    if (tid < 16) {
        float s = 0.0f;
        for (int ww = 0; ww < 12; ww++) s += cw[ww][tid];
        tot[tid] = s;
    }
    __syncthreads();
    if (tid < NN) {
        float nq2 = sqrtf(tot[0]);
        out[2 * BQ + bq * NN + tid] = TEMPF * tot[1 + tid] / fmaxf(nq2, 1e-12f);          // cls_logits
        out[2 * BQ + BQ * NN + bq * NN + tid] = tot[11 + tid] / (1e-16f + sqrtf(tot[6 + tid])); // cls_logits_reweight
    }
}

extern "C" void kernel_launch(void* const* d_in, const int* in_sizes, int n_in,
                              void* d_out, int out_size) {
    const float* feat_shot  = (const float*)d_in[0];
    const float* feat_query = (const float*)d_in[1];
    const float* x_shot     = (const float*)d_in[2];
    const float* x_query    = (const float*)d_in[3];
    const float* w1_task    = (const float*)d_in[4];
    const float* b1_task    = (const float*)d_in[5];
    const float* w2_task    = (const float*)d_in[6];
    const float* b2_task    = (const float*)d_in[7];
    const float* w1_cls     = (const float*)d_in[8];
    const float* b1_cls     = (const float*)d_in[9];
    const float* w2_cls     = (const float*)d_in[10];
    const float* b2_cls     = (const float*)d_in[11];
    float* out = (float*)d_out;

    kMeanShot<<<BB * NN, CC>>>(feat_shot);
    kTaskMean<<<BB, CC>>>();
    kMLP<<<BB + BB * NN, CC>>>(w1_task, b1_task, w2_task, b2_task,
                               w1_cls, b1_cls, w2_cls, b2_cls);
    kShot<<<BB * NN, CC>>>(feat_shot, x_shot);
    kMain<<<BB * QQ, CC>>>(feat_shot, feat_query, x_query, out);
}